// round 2
// baseline (speedup 1.0000x reference)
#include <cuda_runtime.h>

// Problem constants
#define BB 8
#define CC 256
#define HH 8
#define DD 32
#define LL 1024

// 8 MB scratch for z = proj(x): layout [bh][l][d], d contiguous
__device__ float g_z[BB * HH * LL * DD];

// ---------------- f32x2 helpers (Blackwell packed fp32) ----------------
static __device__ __forceinline__ unsigned long long pack2(float x, float y) {
    unsigned long long r;
    asm("mov.b64 %0, {%1, %2};" : "=l"(r) : "f"(x), "f"(y));
    return r;
}
static __device__ __forceinline__ float2 unpack2(unsigned long long v) {
    float2 f;
    asm("mov.b64 {%0, %1}, %2;" : "=f"(f.x), "=f"(f.y) : "l"(v));
    return f;
}
#define FFMA2(d_, a_, b_, c_) \
    asm("fma.rn.f32x2 %0, %1, %2, %3;" : "=l"(d_) : "l"(a_), "l"(b_), "l"(c_))
#define FMUL2(d_, a_, b_) \
    asm("mul.rn.f32x2 %0, %1, %2;" : "=l"(d_) : "l"(a_), "l"(b_))

static __device__ __forceinline__ float ex2f(float x) {
    float r;
    asm("ex2.approx.f32 %0, %1;" : "=f"(r) : "f"(x));
    return r;
}

// ---------------- Kernel 1: per-head 1x1 conv (projection) ----------------
// grid (B*H, 8), 256 threads. Each block computes z[bh, l0:l0+128, :].
// smem: Ws[256*33] (W[h] padded, [c*33+dd]) + xs[256*32] ([c*32+l])
#define PROJ_SMEM ((256 * 33 + 256 * 32) * 4)

__global__ __launch_bounds__(256) void proj_kernel(
    const float* __restrict__ x, const float* __restrict__ Wt,
    const float* __restrict__ bias) {
    extern __shared__ float sm[];
    float* Ws = sm;              // [c*33 + dd]
    float* xs = sm + 256 * 33;   // [c*32 + l]

    const int bh = blockIdx.x;
    const int b = bh >> 3, h = bh & 7;
    const int tid = threadIdx.x;
    const int dd = tid & 31, lg = tid >> 5;

    // Stage W[h]: global coalesced over c, smem stride-33 stores (conflict-free)
    for (int idx = tid; idx < DD * CC; idx += 256) {
        int ddw = idx >> 8, c = idx & 255;
        Ws[c * 33 + ddw] = Wt[(h * DD + ddw) * CC + c];
    }
    const float bv = bias[h * DD + dd];
    const int l0 = blockIdx.y * 128;

    for (int sub = 0; sub < 4; sub++) {
        const int ls = l0 + sub * 32;
        __syncthreads();  // Ws visible (1st iter) / prev compute done
        for (int idx = tid; idx < CC * 32; idx += 256) {
            int c = idx >> 5, l = idx & 31;
            xs[idx] = x[((b * CC + c) << 10) + ls + l];
        }
        __syncthreads();

        unsigned long long acc0 = 0ull, acc1 = 0ull;
        const ulonglong2* xs2 = (const ulonglong2*)xs;
        #pragma unroll 8
        for (int c = 0; c < CC; c++) {
            float w = Ws[c * 33 + dd];
            unsigned long long ww = pack2(w, w);
            ulonglong2 v = xs2[c * 8 + lg];  // xs[c*32 + lg*4 .. +3]
            FFMA2(acc0, ww, v.x, acc0);
            FFMA2(acc1, ww, v.y, acc1);
        }
        float2 a0 = unpack2(acc0), a1 = unpack2(acc1);
        const int lbase = ls + lg * 4;
        float* zp = &g_z[(((unsigned)bh << 10) + lbase) * DD + dd];
        zp[0 * DD] = a0.x + bv;
        zp[1 * DD] = a0.y + bv;
        zp[2 * DD] = a1.x + bv;
        zp[3 * DD] = a1.y + bv;
    }
}

// ---------------- Kernel 2: attention per (bh) with full K/V in smem ------
// grid (B*H, 4), 256 threads; one thread = one query; online softmax.
// smem: zs[1024 * 36] floats (row stride 36 -> 16B aligned rows, 147456 B)
#define ZSTR 36
#define ATTN_SMEM (LL * ZSTR * 4)

__global__ __launch_bounds__(256, 1) void attn_kernel(float* __restrict__ out) {
    extern __shared__ float zs[];
    const int bh = blockIdx.x;
    const int b = bh >> 3, h = bh & 7;
    const int tid = threadIdx.x;

    // Stage all 1024 keys (= Q = V) for this (b,h)
    const float* zsrc = &g_z[(unsigned)bh << 15];
    for (int idx = tid; idx < LL * DD; idx += 256) {
        int l = idx >> 5, j = idx & 31;
        zs[l * ZSTR + j] = zsrc[idx];
    }
    __syncthreads();

    const int qg = (blockIdx.y << 8) + tid;  // global query row
    // scale applied AFTER the dot: (1/sqrt(32)) * log2(e)
    const float qscale = 0.17677669529663687f * 1.4426950408889634f;

    unsigned long long q2[16];
    {
        const ulonglong2* qr = (const ulonglong2*)&zs[qg * ZSTR];
        #pragma unroll
        for (int t = 0; t < 8; t++) {
            ulonglong2 v = qr[t];
            q2[2 * t] = v.x;
            q2[2 * t + 1] = v.y;
        }
    }

    unsigned long long O2[16];
    #pragma unroll
    for (int t = 0; t < 16; t++) O2[t] = 0ull;
    float m = -1e30f, lsum = 0.f;

    for (int kb = 0; kb < LL; kb += 8) {
        float s[8];
        #pragma unroll
        for (int i = 0; i < 8; i++) {
            const ulonglong2* kr = (const ulonglong2*)&zs[(kb + i) * ZSTR];
            unsigned long long acc = 0ull;
            #pragma unroll
            for (int t = 0; t < 8; t++) {
                ulonglong2 v = kr[t];  // broadcast LDS.128, conflict-free
                FFMA2(acc, q2[2 * t], v.x, acc);
                FFMA2(acc, q2[2 * t + 1], v.y, acc);
            }
            float2 a = unpack2(acc);
            s[i] = (a.x + a.y) * qscale;  // logits already in log2 domain
        }
        float mc = s[0];
        #pragma unroll
        for (int i = 1; i < 8; i++) mc = fmaxf(mc, s[i]);
        float mn = fmaxf(m, mc);
        float alpha = ex2f(m - mn);
        m = mn;
        lsum *= alpha;
        unsigned long long aa = pack2(alpha, alpha);
        #pragma unroll
        for (int t = 0; t < 16; t++) FMUL2(O2[t], O2[t], aa);

        #pragma unroll
        for (int i = 0; i < 8; i++) {
            float p = ex2f(s[i] - m);
            lsum += p;
            unsigned long long pp = pack2(p, p);
            const ulonglong2* kr = (const ulonglong2*)&zs[(kb + i) * ZSTR];
            #pragma unroll
            for (int t = 0; t < 8; t++) {
                ulonglong2 v = kr[t];
                FFMA2(O2[2 * t], pp, v.x, O2[2 * t]);
                FFMA2(O2[2 * t + 1], pp, v.y, O2[2 * t + 1]);
            }
        }
    }

    const float inv = 1.0f / lsum;
    __syncthreads();  // everyone done reading zs before reuse
    #pragma unroll
    for (int t = 0; t < 16; t++) {
        float2 a = unpack2(O2[t]);
        zs[tid * ZSTR + 2 * t] = a.x * inv;
        zs[tid * ZSTR + 2 * t + 1] = a.y * inv;
    }
    __syncthreads();

    // out[b, h*32 + j, l] : coalesced over l
    float* ob = out + (((unsigned)(b * (HH * DD) + h * DD)) << 10) + (blockIdx.y << 8);
    for (int idx = tid; idx < 256 * DD; idx += 256) {
        int j = idx >> 8, lq = idx & 255;
        ob[(j << 10) + lq] = zs[lq * ZSTR + j];
    }
}

// ---------------- launch ----------------
extern "C" void kernel_launch(void* const* d_in, const int* in_sizes, int n_in,
                              void* d_out, int out_size) {
    (void)in_sizes; (void)n_in; (void)out_size;
    const float* x = (const float*)d_in[0];   // (8,256,16,64)
    const float* W = (const float*)d_in[1];   // (8,32,256)
    const float* b = (const float*)d_in[2];   // (8,32)
    float* out = (float*)d_out;               // (8,256,16,64)

    cudaFuncSetAttribute(proj_kernel, cudaFuncAttributeMaxDynamicSharedMemorySize,
                         PROJ_SMEM);
    cudaFuncSetAttribute(attn_kernel, cudaFuncAttributeMaxDynamicSharedMemorySize,
                         ATTN_SMEM);

    proj_kernel<<<dim3(BB * HH, 8), 256, PROJ_SMEM>>>(x, W, b);
    attn_kernel<<<dim3(BB * HH, 4), 256, ATTN_SMEM>>>(out);
}

// round 7
// speedup vs baseline: 4.2061x; 4.2061x over previous
#include <cuda_runtime.h>
#include <cstdint>

// Problem constants
#define BB 8
#define CC 256
#define HH 8
#define DD 32
#define LL 1024

// 8 MB scratch for z = proj(x): layout [bh][l][d], d contiguous
__device__ float g_z[BB * HH * LL * DD];

// ======================= helpers =======================
static __device__ __forceinline__ float ex2f(float x) {
    float r;
    asm("ex2.approx.f32 %0, %1;" : "=f"(r) : "f"(x));
    return r;
}
// pack two f32 -> bf16x2 (hi arg in upper half, lo arg in lower half)
static __device__ __forceinline__ uint32_t cvt2(float hi, float lo) {
    uint32_t r;
    asm("cvt.rn.bf16x2.f32 %0, %1, %2;" : "=r"(r) : "f"(hi), "f"(lo));
    return r;
}
static __device__ __forceinline__ float bflo(uint32_t packed) {  // low bf16 -> f32
    return __uint_as_float(packed << 16);
}
static __device__ __forceinline__ float bfhi(uint32_t packed) {  // high bf16 -> f32
    return __uint_as_float(packed & 0xFFFF0000u);
}

// f32x2 helpers for proj kernel
static __device__ __forceinline__ unsigned long long pack2(float x, float y) {
    unsigned long long r;
    asm("mov.b64 %0, {%1, %2};" : "=l"(r) : "f"(x), "f"(y));
    return r;
}
static __device__ __forceinline__ float2 unpack2(unsigned long long v) {
    float2 f;
    asm("mov.b64 {%0, %1}, %2;" : "=f"(f.x), "=f"(f.y) : "l"(v));
    return f;
}
#define FFMA2(d_, a_, b_, c_) \
    asm("fma.rn.f32x2 %0, %1, %2, %3;" : "=l"(d_) : "l"(a_), "l"(b_), "l"(c_))

// bf16 mma m16n8k16, row.col, f32 accumulate (baseline PTX, works on sm_103)
static __device__ __forceinline__ void mma_bf16(float* c, const uint32_t* a,
                                                uint32_t b0, uint32_t b1) {
    asm volatile(
        "mma.sync.aligned.m16n8k16.row.col.f32.bf16.bf16.f32 "
        "{%0,%1,%2,%3}, {%4,%5,%6,%7}, {%8,%9}, {%0,%1,%2,%3};"
        : "+f"(c[0]), "+f"(c[1]), "+f"(c[2]), "+f"(c[3])
        : "r"(a[0]), "r"(a[1]), "r"(a[2]), "r"(a[3]), "r"(b0), "r"(b1));
}

// ======================= Kernel 1: projection (unchanged) =======================
#define PROJ_SMEM ((256 * 33 + 256 * 32) * 4)

__global__ __launch_bounds__(256) void proj_kernel(
    const float* __restrict__ x, const float* __restrict__ Wt,
    const float* __restrict__ bias) {
    extern __shared__ float sm[];
    float* Ws = sm;              // [c*33 + dd]
    float* xs = sm + 256 * 33;   // [c*32 + l]

    const int bh = blockIdx.x;
    const int b = bh >> 3, h = bh & 7;
    const int tid = threadIdx.x;
    const int dd = tid & 31, lg = tid >> 5;

    for (int idx = tid; idx < DD * CC; idx += 256) {
        int ddw = idx >> 8, c = idx & 255;
        Ws[c * 33 + ddw] = Wt[(h * DD + ddw) * CC + c];
    }
    const float bv = bias[h * DD + dd];
    const int l0 = blockIdx.y * 128;

    for (int sub = 0; sub < 4; sub++) {
        const int ls = l0 + sub * 32;
        __syncthreads();
        for (int idx = tid; idx < CC * 32; idx += 256) {
            int c = idx >> 5, l = idx & 31;
            xs[idx] = x[((b * CC + c) << 10) + ls + l];
        }
        __syncthreads();

        unsigned long long acc0 = 0ull, acc1 = 0ull;
        const ulonglong2* xs2 = (const ulonglong2*)xs;
        #pragma unroll 8
        for (int c = 0; c < CC; c++) {
            float w = Ws[c * 33 + dd];
            unsigned long long ww = pack2(w, w);
            ulonglong2 v = xs2[c * 8 + lg];
            FFMA2(acc0, ww, v.x, acc0);
            FFMA2(acc1, ww, v.y, acc1);
        }
        float2 a0 = unpack2(acc0), a1 = unpack2(acc1);
        const int lbase = ls + lg * 4;
        float* zp = &g_z[(((unsigned)bh << 10) + lbase) * DD + dd];
        zp[0 * DD] = a0.x + bv;
        zp[1 * DD] = a0.y + bv;
        zp[2 * DD] = a1.x + bv;
        zp[3 * DD] = a1.y + bv;
    }
}

// ======================= Kernel 2: mma.sync bf16 flash attention ==============
// Block: 128 queries of one (b,h), 8 warps (16 q-rows each); 16 key tiles of 64.
// S = Qhi*Khi + Qhi*Klo + Qlo*Khi     (bf16 split ~ 16-bit mantissa)
// p = exp2(S*c1 - 32); O += Phi*Vhi + Phi*Vlo + Plo*Vhi; lsum exact fp32.
#define MQ 128
#define NK 64
#define NTILE (LL / NK)

// smem byte offsets; strides chosen for conflict-free fragment LDS.32:
// Q/K rows: 80B (20 banks: 20*r mod 32 distinct over r=0..7)
// Vt rows: 144B (36 banks: 36*d mod 32 distinct over d=0..7)
#define QPITCH 80
#define VPITCH 144
#define SM_QHI 0
#define SM_QLO (SM_QHI + MQ * QPITCH)        // 10240
#define SM_KHI (SM_QLO + MQ * QPITCH)        // 20480
#define SM_KLO (SM_KHI + NK * QPITCH)        // 25600
#define SM_VHI (SM_KLO + NK * QPITCH)        // 30720
#define SM_VLO (SM_VHI + DD * VPITCH)        // 35328
#define ATTN_SMEM (SM_VLO + DD * VPITCH)     // 39936

__global__ __launch_bounds__(256, 2) void attn_mma(float* __restrict__ out) {
    extern __shared__ char smc[];
    const int tid = threadIdx.x;
    const int wid = tid >> 5, lane = tid & 31;
    const int g = lane >> 2, cp = lane & 3;
    const int bh = blockIdx.x, b = bh >> 3, h = bh & 7;
    const int l0 = blockIdx.y * MQ;
    const float c1 = 0.17677669529663687f * 1.4426950408889634f;  // scale*log2e

    // ---- stage Q (128 x 32) as bf16 hi/lo ----
    {
        const float4* zq = (const float4*)&g_z[((unsigned)bh << 15) + (unsigned)l0 * DD];
        #pragma unroll
        for (int i = 0; i < 4; i++) {
            int idx = tid + i * 256;               // 0..1023
            float4 v = zq[idx];
            int row = idx >> 3, quad = idx & 7;
            uint32_t ph0 = cvt2(v.y, v.x), ph1 = cvt2(v.w, v.z);
            uint32_t pl0 = cvt2(v.y - bfhi(ph0), v.x - bflo(ph0));
            uint32_t pl1 = cvt2(v.w - bfhi(ph1), v.z - bflo(ph1));
            *(uint2*)(smc + SM_QHI + row * QPITCH + quad * 8) = make_uint2(ph0, ph1);
            *(uint2*)(smc + SM_QLO + row * QPITCH + quad * 8) = make_uint2(pl0, pl1);
        }
    }
    __syncthreads();

    // ---- load Q fragments once (reused for all 16 key tiles) ----
    // A-frag m16n8k16: a0:(r,kp) a1:(r+8,kp) a2:(r,kp+8) a3:(r+8,kp+8)
    uint32_t Ahi[2][4], Alo[2][4];
    {
        const int r0 = wid * 16 + g;
        #pragma unroll
        for (int ks = 0; ks < 2; ks++) {
            int base = ks * 32 + cp * 4;
            Ahi[ks][0] = *(const uint32_t*)(smc + SM_QHI + r0 * QPITCH + base);
            Ahi[ks][1] = *(const uint32_t*)(smc + SM_QHI + (r0 + 8) * QPITCH + base);
            Ahi[ks][2] = *(const uint32_t*)(smc + SM_QHI + r0 * QPITCH + base + 16);
            Ahi[ks][3] = *(const uint32_t*)(smc + SM_QHI + (r0 + 8) * QPITCH + base + 16);
            Alo[ks][0] = *(const uint32_t*)(smc + SM_QLO + r0 * QPITCH + base);
            Alo[ks][1] = *(const uint32_t*)(smc + SM_QLO + (r0 + 8) * QPITCH + base);
            Alo[ks][2] = *(const uint32_t*)(smc + SM_QLO + r0 * QPITCH + base + 16);
            Alo[ks][3] = *(const uint32_t*)(smc + SM_QLO + (r0 + 8) * QPITCH + base + 16);
        }
    }

    float O[4][4];
    #pragma unroll
    for (int nt = 0; nt < 4; nt++)
        #pragma unroll
        for (int j = 0; j < 4; j++) O[nt][j] = 0.f;
    float lsum0 = 0.f, lsum1 = 0.f;

    for (int t = 0; t < NTILE; t++) {
        __syncthreads();  // previous tile's reads done before restaging
        // ---- stage K tile (64 x 32) hi/lo + transposed V (32 x 64) hi/lo ----
        {
            const float4* zk =
                (const float4*)&g_z[((unsigned)bh << 15) + (unsigned)(t * NK) * DD];
            #pragma unroll
            for (int i = 0; i < 2; i++) {
                int idx = tid + i * 256;           // 0..511
                float4 v = zk[idx];
                int k = idx >> 3, quad = idx & 7;
                uint32_t ph0 = cvt2(v.y, v.x), ph1 = cvt2(v.w, v.z);
                uint32_t pl0 = cvt2(v.y - bfhi(ph0), v.x - bflo(ph0));
                uint32_t pl1 = cvt2(v.w - bfhi(ph1), v.z - bflo(ph1));
                *(uint2*)(smc + SM_KHI + k * QPITCH + quad * 8) = make_uint2(ph0, ph1);
                *(uint2*)(smc + SM_KLO + k * QPITCH + quad * 8) = make_uint2(pl0, pl1);
                // V^T[d][k]
                int d0 = quad * 4;
                uint16_t* vh = (uint16_t*)(smc + SM_VHI + k * 2);
                uint16_t* vl = (uint16_t*)(smc + SM_VLO + k * 2);
                vh[(d0 + 0) * (VPITCH / 2)] = (uint16_t)(ph0 & 0xFFFF);
                vh[(d0 + 1) * (VPITCH / 2)] = (uint16_t)(ph0 >> 16);
                vh[(d0 + 2) * (VPITCH / 2)] = (uint16_t)(ph1 & 0xFFFF);
                vh[(d0 + 3) * (VPITCH / 2)] = (uint16_t)(ph1 >> 16);
                vl[(d0 + 0) * (VPITCH / 2)] = (uint16_t)(pl0 & 0xFFFF);
                vl[(d0 + 1) * (VPITCH / 2)] = (uint16_t)(pl0 >> 16);
                vl[(d0 + 2) * (VPITCH / 2)] = (uint16_t)(pl1 & 0xFFFF);
                vl[(d0 + 3) * (VPITCH / 2)] = (uint16_t)(pl1 >> 16);
            }
        }
        __syncthreads();

        // ---- QK^T: S (16 x 64 per warp), 3-term split ----
        float S[8][4];
        #pragma unroll
        for (int n = 0; n < 8; n++)
            #pragma unroll
            for (int j = 0; j < 4; j++) S[n][j] = 0.f;

        #pragma unroll
        for (int ks = 0; ks < 2; ks++) {
            #pragma unroll
            for (int n = 0; n < 8; n++) {
                const char* kb = smc + (n * 8 + g) * QPITCH + ks * 32 + cp * 4;
                uint32_t bh0 = *(const uint32_t*)(kb + SM_KHI);
                uint32_t bh1 = *(const uint32_t*)(kb + SM_KHI + 16);
                uint32_t bl0 = *(const uint32_t*)(kb + SM_KLO);
                uint32_t bl1 = *(const uint32_t*)(kb + SM_KLO + 16);
                mma_bf16(S[n], Ahi[ks], bh0, bh1);
                mma_bf16(S[n], Ahi[ks], bl0, bl1);
                mma_bf16(S[n], Alo[ks], bh0, bh1);
            }
        }

        // ---- softmax (fixed -32 offset) + pack P as A-frags for PV ----
        uint32_t Phi[4][4], Plo[4][4];
        #pragma unroll
        for (int ks = 0; ks < 4; ks++) {
            float p[2][4];
            #pragma unroll
            for (int half = 0; half < 2; half++) {
                int jn = 2 * ks + half;
                #pragma unroll
                for (int j = 0; j < 4; j++)
                    p[half][j] = ex2f(fmaf(S[jn][j], c1, -32.0f));
            }
            lsum0 += p[0][0] + p[0][1] + p[1][0] + p[1][1];
            lsum1 += p[0][2] + p[0][3] + p[1][2] + p[1][3];
            // A-frag: a0={c0,c1}@2ks  a1={c2,c3}@2ks  a2={c0,c1}@2ks+1  a3={c2,c3}@2ks+1
            #pragma unroll
            for (int j = 0; j < 4; j++) {
                int half = j >> 1, lohalf = (j & 1) * 2;
                float e0 = p[half][lohalf], e1 = p[half][lohalf + 1];
                uint32_t ph = cvt2(e1, e0);
                Phi[ks][j] = ph;
                Plo[ks][j] = cvt2(e1 - bfhi(ph), e0 - bflo(ph));
            }
        }

        // ---- PV: O (16 x 32 per warp) += P * V^T, 3-term split ----
        #pragma unroll
        for (int nt = 0; nt < 4; nt++) {
            #pragma unroll
            for (int ks = 0; ks < 4; ks++) {
                const char* vb = smc + (nt * 8 + g) * VPITCH + ks * 32 + cp * 4;
                uint32_t bh0 = *(const uint32_t*)(vb + SM_VHI);
                uint32_t bh1 = *(const uint32_t*)(vb + SM_VHI + 16);
                uint32_t bl0 = *(const uint32_t*)(vb + SM_VLO);
                uint32_t bl1 = *(const uint32_t*)(vb + SM_VLO + 16);
                mma_bf16(O[nt], Phi[ks], bh0, bh1);
                mma_bf16(O[nt], Phi[ks], bl0, bl1);
                mma_bf16(O[nt], Plo[ks], bh0, bh1);
            }
        }
    }

    // ---- normalize + store ----
    lsum0 += __shfl_xor_sync(0xFFFFFFFFu, lsum0, 1);
    lsum0 += __shfl_xor_sync(0xFFFFFFFFu, lsum0, 2);
    lsum1 += __shfl_xor_sync(0xFFFFFFFFu, lsum1, 1);
    lsum1 += __shfl_xor_sync(0xFFFFFFFFu, lsum1, 2);
    const float inv0 = 1.0f / lsum0, inv1 = 1.0f / lsum1;

    const int q0 = l0 + wid * 16 + g, q1 = q0 + 8;
    const unsigned cbase = (unsigned)(b * (HH * DD) + h * DD);
    #pragma unroll
    for (int nt = 0; nt < 4; nt++) {
        int d = nt * 8 + 2 * cp;
        out[((cbase + d) << 10) + q0] = O[nt][0] * inv0;
        out[((cbase + d + 1) << 10) + q0] = O[nt][1] * inv0;
        out[((cbase + d) << 10) + q1] = O[nt][2] * inv1;
        out[((cbase + d + 1) << 10) + q1] = O[nt][3] * inv1;
    }
}

// ======================= launch =======================
extern "C" void kernel_launch(void* const* d_in, const int* in_sizes, int n_in,
                              void* d_out, int out_size) {
    (void)in_sizes; (void)n_in; (void)out_size;
    const float* x = (const float*)d_in[0];   // (8,256,16,64)
    const float* W = (const float*)d_in[1];   // (8,32,256)
    const float* b = (const float*)d_in[2];   // (8,32)
    float* out = (float*)d_out;               // (8,256,16,64)

    cudaFuncSetAttribute(proj_kernel, cudaFuncAttributeMaxDynamicSharedMemorySize,
                         PROJ_SMEM);
    cudaFuncSetAttribute(attn_mma, cudaFuncAttributeMaxDynamicSharedMemorySize,
                         ATTN_SMEM);

    proj_kernel<<<dim3(BB * HH, 8), 256, PROJ_SMEM>>>(x, W, b);
    attn_mma<<<dim3(BB * HH, LL / MQ), 256, ATTN_SMEM>>>(out);
}

// round 13
// speedup vs baseline: 6.2216x; 1.4792x over previous
#include <cuda_runtime.h>
#include <cstdint>

// Problem constants
#define BB 8
#define CC 256
#define HH 8
#define DD 32
#define LL 1024

// z stored pre-split as packed bf16x2 (d-pairs): [bh][l][16] uint32, 4MB each
__device__ uint32_t g_zh[BB * HH * LL * 16];
__device__ uint32_t g_zl[BB * HH * LL * 16];

// ======================= helpers =======================
static __device__ __forceinline__ float ex2f(float x) {
    float r;
    asm("ex2.approx.f32 %0, %1;" : "=f"(r) : "f"(x));
    return r;
}
// pack two f32 -> bf16x2 (hi arg in upper half, lo arg in lower half)
static __device__ __forceinline__ uint32_t cvt2(float hi, float lo) {
    uint32_t r;
    asm("cvt.rn.bf16x2.f32 %0, %1, %2;" : "=r"(r) : "f"(hi), "f"(lo));
    return r;
}
static __device__ __forceinline__ float bflo(uint32_t packed) {  // low bf16 -> f32
    return __uint_as_float(packed << 16);
}
static __device__ __forceinline__ float bfhi(uint32_t packed) {  // high bf16 -> f32
    return __uint_as_float(packed & 0xFFFF0000u);
}

// bf16 mma m16n8k16, row.col, f32 accumulate (baseline PTX, works on sm_103)
static __device__ __forceinline__ void mma_bf16(float* c, const uint32_t* a,
                                                uint32_t b0, uint32_t b1) {
    asm volatile(
        "mma.sync.aligned.m16n8k16.row.col.f32.bf16.bf16.f32 "
        "{%0,%1,%2,%3}, {%4,%5,%6,%7}, {%8,%9}, {%0,%1,%2,%3};"
        : "+f"(c[0]), "+f"(c[1]), "+f"(c[2]), "+f"(c[3])
        : "r"(a[0]), "r"(a[1]), "r"(a[2]), "r"(a[3]), "r"(b0), "r"(b1));
}
static __device__ __forceinline__ uint32_t lds32(const char* p) {
    return *(const uint32_t*)p;
}
static __device__ __forceinline__ void sts32(char* p, uint32_t v) {
    *(uint32_t*)p = v;
}

// ======================= Kernel 1: tensor-core projection ==================
// Per block: 128 l-rows x 32 d of one (b,h). z = X^T[128,256] * W[h]^T.
// 3-term bf16 split: Xhi*Whi + Xhi*Wlo + Xlo*Whi, fp32 accum, + bias.
// Output: packed bf16x2 hi/lo (d-pairs) into g_zh/g_zl.
#define PW_PITCH 528                       // 132 words = 4 mod 32: banks 4g+cp bijective
#define PA_PITCH 148                       // 37 words odd: conflict-free 4B transpose stores
#define PSM_WHI 0
#define PSM_WLO (PSM_WHI + 32 * PW_PITCH)  // 16896
#define PSM_AHI (PSM_WLO + 32 * PW_PITCH)  // 33792
#define PSM_ALO (PSM_AHI + 128 * PA_PITCH) // 52736
#define PROJ_SMEM (PSM_ALO + 128 * PA_PITCH) // 71680

__global__ __launch_bounds__(256, 2) void proj_mma(
    const float* __restrict__ x, const float* __restrict__ Wt,
    const float* __restrict__ bias) {
    extern __shared__ char smc[];
    const int tid = threadIdx.x;
    const int wid = tid >> 5, lane = tid & 31;
    const int g = lane >> 2, cp = lane & 3;
    const int bh = blockIdx.x, b = bh >> 3, h = bh & 7;
    const int l0 = blockIdx.y * 128;

    // ---- stage W[h] (32 x 256) as bf16 hi/lo (PW_PITCH mult of 16: uint2 ok) ----
    #pragma unroll
    for (int i = 0; i < 8; i++) {
        int idx = tid + i * 256;           // 0..2047
        int d = idx >> 6, cq = idx & 63;   // cq = group of 4 c's
        float4 v = *(const float4*)&Wt[(h * 32 + d) * 256 + cq * 4];
        uint32_t ph0 = cvt2(v.y, v.x), ph1 = cvt2(v.w, v.z);
        uint32_t pl0 = cvt2(v.y - bfhi(ph0), v.x - bflo(ph0));
        uint32_t pl1 = cvt2(v.w - bfhi(ph1), v.z - bflo(ph1));
        *(uint2*)(smc + PSM_WHI + d * PW_PITCH + cq * 8) = make_uint2(ph0, ph1);
        *(uint2*)(smc + PSM_WLO + d * PW_PITCH + cq * 8) = make_uint2(pl0, pl1);
    }

    float O[4][4];
    #pragma unroll
    for (int n = 0; n < 4; n++)
        #pragma unroll
        for (int j = 0; j < 4; j++) O[n][j] = 0.f;

    const int r0 = wid * 16 + g;

    for (int kc = 0; kc < 4; kc++) {       // K chunks of 64 c
        __syncthreads();                    // W ready (kc=0) / prev chunk mma done
        // ---- stage transposed X tile: A[l][c] (128 x 64) hi/lo bf16 ----
        // thread: one l, 4 consecutive c. PA_PITCH = 4 mod 8 -> MUST use 4B stores.
        #pragma unroll
        for (int i = 0; i < 8; i++) {
            int idx = tid + i * 256;        // 0..2047
            int l = idx & 127, cg = idx >> 7;  // cg = group of 4 c
            const float* xp = &x[((unsigned)(b * CC + kc * 64 + cg * 4) << 10) + l0 + l];
            float v0 = xp[0];
            float v1 = xp[1 << 10];
            float v2 = xp[2 << 10];
            float v3 = xp[3 << 10];
            uint32_t ph0 = cvt2(v1, v0), ph1 = cvt2(v3, v2);
            uint32_t pl0 = cvt2(v1 - bfhi(ph0), v0 - bflo(ph0));
            uint32_t pl1 = cvt2(v3 - bfhi(ph1), v2 - bflo(ph1));
            char* ah = smc + PSM_AHI + l * PA_PITCH + cg * 8;
            char* al = smc + PSM_ALO + l * PA_PITCH + cg * 8;
            sts32(ah, ph0);
            sts32(ah + 4, ph1);
            sts32(al, pl0);
            sts32(al + 4, pl1);
        }
        __syncthreads();

        // ---- mma: 4 k-steps x 4 n-tiles x 3 split terms ----
        #pragma unroll
        for (int ks = 0; ks < 4; ks++) {
            uint32_t Ahi[4], Alo[4];
            const char* ab = smc + r0 * PA_PITCH + ks * 32 + cp * 4;
            Ahi[0] = lds32(ab + PSM_AHI);
            Ahi[1] = lds32(ab + PSM_AHI + 8 * PA_PITCH);
            Ahi[2] = lds32(ab + PSM_AHI + 16);
            Ahi[3] = lds32(ab + PSM_AHI + 8 * PA_PITCH + 16);
            Alo[0] = lds32(ab + PSM_ALO);
            Alo[1] = lds32(ab + PSM_ALO + 8 * PA_PITCH);
            Alo[2] = lds32(ab + PSM_ALO + 16);
            Alo[3] = lds32(ab + PSM_ALO + 8 * PA_PITCH + 16);
            #pragma unroll
            for (int n = 0; n < 4; n++) {
                const char* wb = smc + (n * 8 + g) * PW_PITCH + kc * 128 + ks * 32 + cp * 4;
                uint32_t bh0 = lds32(wb + PSM_WHI);
                uint32_t bh1 = lds32(wb + PSM_WHI + 16);
                uint32_t bl0 = lds32(wb + PSM_WLO);
                uint32_t bl1 = lds32(wb + PSM_WLO + 16);
                mma_bf16(O[n], Ahi, bh0, bh1);
                mma_bf16(O[n], Ahi, bl0, bl1);
                mma_bf16(O[n], Alo, bh0, bh1);
            }
        }
    }

    // ---- epilogue: + bias, split hi/lo, store packed d-pairs ----
    #pragma unroll
    for (int n = 0; n < 4; n++) {
        float2 bv = *(const float2*)&bias[h * 32 + n * 8 + cp * 2];
        float e0 = O[n][0] + bv.x, e1 = O[n][1] + bv.y;   // row r0
        float e2 = O[n][2] + bv.x, e3 = O[n][3] + bv.y;   // row r0+8
        uint32_t p0 = cvt2(e1, e0), p1 = cvt2(e3, e2);
        uint32_t q0 = cvt2(e1 - bfhi(p0), e0 - bflo(p0));
        uint32_t q1 = cvt2(e3 - bfhi(p1), e2 - bflo(p1));
        unsigned i0 = (((unsigned)bh << 10) + l0 + r0) * 16 + n * 4 + cp;
        g_zh[i0] = p0;
        g_zl[i0] = q0;
        g_zh[i0 + 8 * 16] = p1;
        g_zl[i0 + 8 * 16] = q1;
    }
}

// ======================= Kernel 2: mma.sync bf16 flash attention ==============
// Block: 128 queries of one (b,h), 8 warps (16 q-rows each); 16 key tiles of 64.
// S = Qhi*Khi + Qhi*Klo + Qlo*Khi; p = exp2(S*c1 - 32);
// O += Phi*Vhi + Phi*Vlo + Plo*Vhi; lsum exact fp32.
#define MQ 128
#define NK 64
#define NTILE (LL / NK)

#define QPITCH 80
#define VPITCH 144
#define SM_QHI 0
#define SM_QLO (SM_QHI + MQ * QPITCH)        // 10240
#define SM_KHI (SM_QLO + MQ * QPITCH)        // 20480
#define SM_KLO (SM_KHI + NK * QPITCH)        // 25600
#define SM_VHI (SM_KLO + NK * QPITCH)        // 30720
#define SM_VLO (SM_VHI + DD * VPITCH)        // 35328
#define ATTN_SMEM (SM_VLO + DD * VPITCH)     // 39936

__global__ __launch_bounds__(256, 2) void attn_mma(float* __restrict__ out) {
    extern __shared__ char smc[];
    const int tid = threadIdx.x;
    const int wid = tid >> 5, lane = tid & 31;
    const int g = lane >> 2, cp = lane & 3;
    const int bh = blockIdx.x, b = bh >> 3, h = bh & 7;
    const int l0 = blockIdx.y * MQ;
    const float c1 = 0.17677669529663687f * 1.4426950408889634f;  // scale*log2e

    const uint4* zh4 = (const uint4*)g_zh;
    const uint4* zl4 = (const uint4*)g_zl;

    // ---- stage Q (128 rows x 16 u32) hi/lo: pure uint4 copies ----
    #pragma unroll
    for (int i = 0; i < 2; i++) {
        int idx = tid + i * 256;               // 0..511
        int row = idx >> 2, q4 = idx & 3;
        unsigned gi = ((((unsigned)bh << 10) + l0 + row) << 2) + q4;
        *(uint4*)(smc + SM_QHI + row * QPITCH + q4 * 16) = zh4[gi];
        *(uint4*)(smc + SM_QLO + row * QPITCH + q4 * 16) = zl4[gi];
    }
    __syncthreads();

    // ---- load Q fragments once (reused for all 16 key tiles) ----
    uint32_t Ahi[2][4], Alo[2][4];
    {
        const int r0 = wid * 16 + g;
        #pragma unroll
        for (int ks = 0; ks < 2; ks++) {
            int base = ks * 32 + cp * 4;
            Ahi[ks][0] = lds32(smc + SM_QHI + r0 * QPITCH + base);
            Ahi[ks][1] = lds32(smc + SM_QHI + (r0 + 8) * QPITCH + base);
            Ahi[ks][2] = lds32(smc + SM_QHI + r0 * QPITCH + base + 16);
            Ahi[ks][3] = lds32(smc + SM_QHI + (r0 + 8) * QPITCH + base + 16);
            Alo[ks][0] = lds32(smc + SM_QLO + r0 * QPITCH + base);
            Alo[ks][1] = lds32(smc + SM_QLO + (r0 + 8) * QPITCH + base);
            Alo[ks][2] = lds32(smc + SM_QLO + r0 * QPITCH + base + 16);
            Alo[ks][3] = lds32(smc + SM_QLO + (r0 + 8) * QPITCH + base + 16);
        }
    }

    float O[4][4];
    #pragma unroll
    for (int nt = 0; nt < 4; nt++)
        #pragma unroll
        for (int j = 0; j < 4; j++) O[nt][j] = 0.f;
    float lsum0 = 0.f, lsum1 = 0.f;

    for (int t = 0; t < NTILE; t++) {
        __syncthreads();  // previous tile's reads done before restaging
        // ---- stage K tile (64 rows) hi/lo + transposed V (32 x 64) hi/lo ----
        {
            int k = tid >> 2, q4 = tid & 3;
            unsigned gi = ((((unsigned)bh << 10) + t * NK + k) << 2) + q4;
            uint4 hv = zh4[gi];
            uint4 lv = zl4[gi];
            *(uint4*)(smc + SM_KHI + k * QPITCH + q4 * 16) = hv;
            *(uint4*)(smc + SM_KLO + k * QPITCH + q4 * 16) = lv;
            // V^T[d][k]: d = q4*8 + 0..7
            uint16_t* vh = (uint16_t*)(smc + SM_VHI + k * 2);
            uint16_t* vl = (uint16_t*)(smc + SM_VLO + k * 2);
            int d0 = q4 * 8;
            vh[(d0 + 0) * (VPITCH / 2)] = (uint16_t)(hv.x & 0xFFFF);
            vh[(d0 + 1) * (VPITCH / 2)] = (uint16_t)(hv.x >> 16);
            vh[(d0 + 2) * (VPITCH / 2)] = (uint16_t)(hv.y & 0xFFFF);
            vh[(d0 + 3) * (VPITCH / 2)] = (uint16_t)(hv.y >> 16);
            vh[(d0 + 4) * (VPITCH / 2)] = (uint16_t)(hv.z & 0xFFFF);
            vh[(d0 + 5) * (VPITCH / 2)] = (uint16_t)(hv.z >> 16);
            vh[(d0 + 6) * (VPITCH / 2)] = (uint16_t)(hv.w & 0xFFFF);
            vh[(d0 + 7) * (VPITCH / 2)] = (uint16_t)(hv.w >> 16);
            vl[(d0 + 0) * (VPITCH / 2)] = (uint16_t)(lv.x & 0xFFFF);
            vl[(d0 + 1) * (VPITCH / 2)] = (uint16_t)(lv.x >> 16);
            vl[(d0 + 2) * (VPITCH / 2)] = (uint16_t)(lv.y & 0xFFFF);
            vl[(d0 + 3) * (VPITCH / 2)] = (uint16_t)(lv.y >> 16);
            vl[(d0 + 4) * (VPITCH / 2)] = (uint16_t)(lv.z & 0xFFFF);
            vl[(d0 + 5) * (VPITCH / 2)] = (uint16_t)(lv.z >> 16);
            vl[(d0 + 6) * (VPITCH / 2)] = (uint16_t)(lv.w & 0xFFFF);
            vl[(d0 + 7) * (VPITCH / 2)] = (uint16_t)(lv.w >> 16);
        }
        __syncthreads();

        // ---- QK^T: S (16 x 64 per warp), 3-term split ----
        float S[8][4];
        #pragma unroll
        for (int n = 0; n < 8; n++)
            #pragma unroll
            for (int j = 0; j < 4; j++) S[n][j] = 0.f;

        #pragma unroll
        for (int ks = 0; ks < 2; ks++) {
            #pragma unroll
            for (int n = 0; n < 8; n++) {
                const char* kb = smc + (n * 8 + g) * QPITCH + ks * 32 + cp * 4;
                uint32_t bh0 = lds32(kb + SM_KHI);
                uint32_t bh1 = lds32(kb + SM_KHI + 16);
                uint32_t bl0 = lds32(kb + SM_KLO);
                uint32_t bl1 = lds32(kb + SM_KLO + 16);
                mma_bf16(S[n], Ahi[ks], bh0, bh1);
                mma_bf16(S[n], Ahi[ks], bl0, bl1);
                mma_bf16(S[n], Alo[ks], bh0, bh1);
            }
        }

        // ---- softmax (fixed -32 offset) + pack P as A-frags for PV ----
        uint32_t Phi[4][4], Plo[4][4];
        #pragma unroll
        for (int ks = 0; ks < 4; ks++) {
            float p[2][4];
            #pragma unroll
            for (int half = 0; half < 2; half++) {
                int jn = 2 * ks + half;
                #pragma unroll
                for (int j = 0; j < 4; j++)
                    p[half][j] = ex2f(fmaf(S[jn][j], c1, -32.0f));
            }
            lsum0 += p[0][0] + p[0][1] + p[1][0] + p[1][1];
            lsum1 += p[0][2] + p[0][3] + p[1][2] + p[1][3];
            #pragma unroll
            for (int j = 0; j < 4; j++) {
                int half = j >> 1, lohalf = (j & 1) * 2;
                float e0 = p[half][lohalf], e1 = p[half][lohalf + 1];
                uint32_t ph = cvt2(e1, e0);
                Phi[ks][j] = ph;
                Plo[ks][j] = cvt2(e1 - bfhi(ph), e0 - bflo(ph));
            }
        }

        // ---- PV: O (16 x 32 per warp) += P * V^T, 3-term split ----
        #pragma unroll
        for (int nt = 0; nt < 4; nt++) {
            #pragma unroll
            for (int ks = 0; ks < 4; ks++) {
                const char* vb = smc + (nt * 8 + g) * VPITCH + ks * 32 + cp * 4;
                uint32_t bh0 = lds32(vb + SM_VHI);
                uint32_t bh1 = lds32(vb + SM_VHI + 16);
                uint32_t bl0 = lds32(vb + SM_VLO);
                uint32_t bl1 = lds32(vb + SM_VLO + 16);
                mma_bf16(O[nt], Phi[ks], bh0, bh1);
                mma_bf16(O[nt], Phi[ks], bl0, bl1);
                mma_bf16(O[nt], Plo[ks], bh0, bh1);
            }
        }
    }

    // ---- normalize + store ----
    lsum0 += __shfl_xor_sync(0xFFFFFFFFu, lsum0, 1);
    lsum0 += __shfl_xor_sync(0xFFFFFFFFu, lsum0, 2);
    lsum1 += __shfl_xor_sync(0xFFFFFFFFu, lsum1, 1);
    lsum1 += __shfl_xor_sync(0xFFFFFFFFu, lsum1, 2);
    const float inv0 = 1.0f / lsum0, inv1 = 1.0f / lsum1;

    const int q0 = l0 + wid * 16 + g, q1 = q0 + 8;
    const unsigned cbase = (unsigned)(b * (HH * DD) + h * DD);
    #pragma unroll
    for (int nt = 0; nt < 4; nt++) {
        int d = nt * 8 + 2 * cp;
        out[((cbase + d) << 10) + q0] = O[nt][0] * inv0;
        out[((cbase + d + 1) << 10) + q0] = O[nt][1] * inv0;
        out[((cbase + d) << 10) + q1] = O[nt][2] * inv1;
        out[((cbase + d + 1) << 10) + q1] = O[nt][3] * inv1;
    }
}

// ======================= launch =======================
extern "C" void kernel_launch(void* const* d_in, const int* in_sizes, int n_in,
                              void* d_out, int out_size) {
    (void)in_sizes; (void)n_in; (void)out_size;
    const float* x = (const float*)d_in[0];   // (8,256,16,64)
    const float* W = (const float*)d_in[1];   // (8,32,256)
    const float* b = (const float*)d_in[2];   // (8,32)
    float* out = (float*)d_out;               // (8,256,16,64)

    cudaFuncSetAttribute(proj_mma, cudaFuncAttributeMaxDynamicSharedMemorySize,
                         PROJ_SMEM);
    cudaFuncSetAttribute(attn_mma, cudaFuncAttributeMaxDynamicSharedMemorySize,
                         ATTN_SMEM);

    proj_mma<<<dim3(BB * HH, 8), 256, PROJ_SMEM>>>(x, W, b);
    attn_mma<<<dim3(BB * HH, LL / MQ), 256, ATTN_SMEM>>>(out);
}

// round 14
// speedup vs baseline: 7.4945x; 1.2046x over previous
#include <cuda_runtime.h>
#include <cstdint>

// Problem constants
#define BB 8
#define CC 256
#define HH 8
#define DD 32
#define LL 1024

// z stored pre-split as packed bf16x2 (d-pairs): [bh][l][16] uint32, 4MB each
__device__ uint32_t g_zh[BB * HH * LL * 16];
__device__ uint32_t g_zl[BB * HH * LL * 16];

// ======================= helpers =======================
static __device__ __forceinline__ float ex2f(float x) {
    float r;
    asm("ex2.approx.f32 %0, %1;" : "=f"(r) : "f"(x));
    return r;
}
// pack two f32 -> bf16x2 (hi arg in upper half, lo arg in lower half)
static __device__ __forceinline__ uint32_t cvt2(float hi, float lo) {
    uint32_t r;
    asm("cvt.rn.bf16x2.f32 %0, %1, %2;" : "=r"(r) : "f"(hi), "f"(lo));
    return r;
}
static __device__ __forceinline__ float bflo(uint32_t packed) {  // low bf16 -> f32
    return __uint_as_float(packed << 16);
}
static __device__ __forceinline__ float bfhi(uint32_t packed) {  // high bf16 -> f32
    return __uint_as_float(packed & 0xFFFF0000u);
}
static __device__ __forceinline__ uint32_t smem_u32(const void* p) {
    uint32_t a;
    asm("{ .reg .u64 t; cvta.to.shared.u64 t, %1; cvt.u32.u64 %0, t; }"
        : "=r"(a) : "l"(p));
    return a;
}

// bf16 mma m16n8k16, row.col, f32 accumulate (baseline PTX, works on sm_103)
static __device__ __forceinline__ void mma_bf16(float* c, const uint32_t* a,
                                                uint32_t b0, uint32_t b1) {
    asm volatile(
        "mma.sync.aligned.m16n8k16.row.col.f32.bf16.bf16.f32 "
        "{%0,%1,%2,%3}, {%4,%5,%6,%7}, {%8,%9}, {%0,%1,%2,%3};"
        : "+f"(c[0]), "+f"(c[1]), "+f"(c[2]), "+f"(c[3])
        : "r"(a[0]), "r"(a[1]), "r"(a[2]), "r"(a[3]), "r"(b0), "r"(b1));
}
// ldmatrix 4-tile loads (baseline PTX sm_75+)
static __device__ __forceinline__ void ldsm4(uint32_t* r, uint32_t a) {
    asm volatile("ldmatrix.sync.aligned.m8n8.x4.shared.b16 {%0,%1,%2,%3}, [%4];"
                 : "=r"(r[0]), "=r"(r[1]), "=r"(r[2]), "=r"(r[3]) : "r"(a));
}
static __device__ __forceinline__ void ldsm4t(uint32_t* r, uint32_t a) {
    asm volatile("ldmatrix.sync.aligned.m8n8.x4.trans.shared.b16 {%0,%1,%2,%3}, [%4];"
                 : "=r"(r[0]), "=r"(r[1]), "=r"(r[2]), "=r"(r[3]) : "r"(a));
}
static __device__ __forceinline__ uint32_t lds32(const char* p) {
    return *(const uint32_t*)p;
}
static __device__ __forceinline__ void sts32(char* p, uint32_t v) {
    *(uint32_t*)p = v;
}

// ======================= Kernel 1: tensor-core projection ==================
// Per block: 128 l-rows x 32 d of one (b,h). z = X^T[128,256] * W[h]^T.
// 3-term bf16 split: Xhi*Whi + Xhi*Wlo + Xlo*Whi, fp32 accum, + bias.
// Output: packed bf16x2 hi/lo (d-pairs) into g_zh/g_zl.
#define PW_PITCH 528                       // 132 words = 4 mod 32: banks 4g+cp bijective
#define PA_PITCH 148                       // 37 words odd: conflict-free 4B transpose stores
#define PSM_WHI 0
#define PSM_WLO (PSM_WHI + 32 * PW_PITCH)  // 16896
#define PSM_AHI (PSM_WLO + 32 * PW_PITCH)  // 33792
#define PSM_ALO (PSM_AHI + 128 * PA_PITCH) // 52736
#define PROJ_SMEM (PSM_ALO + 128 * PA_PITCH) // 71680

__global__ __launch_bounds__(256, 2) void proj_mma(
    const float* __restrict__ x, const float* __restrict__ Wt,
    const float* __restrict__ bias) {
    extern __shared__ char smc[];
    const int tid = threadIdx.x;
    const int wid = tid >> 5, lane = tid & 31;
    const int g = lane >> 2, cp = lane & 3;
    const int bh = blockIdx.x, b = bh >> 3, h = bh & 7;
    const int l0 = blockIdx.y * 128;

    // ---- stage W[h] (32 x 256) as bf16 hi/lo (PW_PITCH mult of 16: uint2 ok) ----
    #pragma unroll
    for (int i = 0; i < 8; i++) {
        int idx = tid + i * 256;           // 0..2047
        int d = idx >> 6, cq = idx & 63;   // cq = group of 4 c's
        float4 v = *(const float4*)&Wt[(h * 32 + d) * 256 + cq * 4];
        uint32_t ph0 = cvt2(v.y, v.x), ph1 = cvt2(v.w, v.z);
        uint32_t pl0 = cvt2(v.y - bfhi(ph0), v.x - bflo(ph0));
        uint32_t pl1 = cvt2(v.w - bfhi(ph1), v.z - bflo(ph1));
        *(uint2*)(smc + PSM_WHI + d * PW_PITCH + cq * 8) = make_uint2(ph0, ph1);
        *(uint2*)(smc + PSM_WLO + d * PW_PITCH + cq * 8) = make_uint2(pl0, pl1);
    }

    float O[4][4];
    #pragma unroll
    for (int n = 0; n < 4; n++)
        #pragma unroll
        for (int j = 0; j < 4; j++) O[n][j] = 0.f;

    const int r0 = wid * 16 + g;

    for (int kc = 0; kc < 4; kc++) {       // K chunks of 64 c
        __syncthreads();                    // W ready (kc=0) / prev chunk mma done
        // ---- stage transposed X tile: A[l][c] (128 x 64) hi/lo bf16 ----
        // thread: one l, 4 consecutive c. PA_PITCH = 4 mod 8 -> MUST use 4B stores.
        #pragma unroll
        for (int i = 0; i < 8; i++) {
            int idx = tid + i * 256;        // 0..2047
            int l = idx & 127, cg = idx >> 7;  // cg = group of 4 c
            const float* xp = &x[((unsigned)(b * CC + kc * 64 + cg * 4) << 10) + l0 + l];
            float v0 = xp[0];
            float v1 = xp[1 << 10];
            float v2 = xp[2 << 10];
            float v3 = xp[3 << 10];
            uint32_t ph0 = cvt2(v1, v0), ph1 = cvt2(v3, v2);
            uint32_t pl0 = cvt2(v1 - bfhi(ph0), v0 - bflo(ph0));
            uint32_t pl1 = cvt2(v3 - bfhi(ph1), v2 - bflo(ph1));
            char* ah = smc + PSM_AHI + l * PA_PITCH + cg * 8;
            char* al = smc + PSM_ALO + l * PA_PITCH + cg * 8;
            sts32(ah, ph0);
            sts32(ah + 4, ph1);
            sts32(al, pl0);
            sts32(al + 4, pl1);
        }
        __syncthreads();

        // ---- mma: 4 k-steps x 4 n-tiles x 3 split terms ----
        #pragma unroll
        for (int ks = 0; ks < 4; ks++) {
            uint32_t Ahi[4], Alo[4];
            const char* ab = smc + r0 * PA_PITCH + ks * 32 + cp * 4;
            Ahi[0] = lds32(ab + PSM_AHI);
            Ahi[1] = lds32(ab + PSM_AHI + 8 * PA_PITCH);
            Ahi[2] = lds32(ab + PSM_AHI + 16);
            Ahi[3] = lds32(ab + PSM_AHI + 8 * PA_PITCH + 16);
            Alo[0] = lds32(ab + PSM_ALO);
            Alo[1] = lds32(ab + PSM_ALO + 8 * PA_PITCH);
            Alo[2] = lds32(ab + PSM_ALO + 16);
            Alo[3] = lds32(ab + PSM_ALO + 8 * PA_PITCH + 16);
            #pragma unroll
            for (int n = 0; n < 4; n++) {
                const char* wb = smc + (n * 8 + g) * PW_PITCH + kc * 128 + ks * 32 + cp * 4;
                uint32_t bh0 = lds32(wb + PSM_WHI);
                uint32_t bh1 = lds32(wb + PSM_WHI + 16);
                uint32_t bl0 = lds32(wb + PSM_WLO);
                uint32_t bl1 = lds32(wb + PSM_WLO + 16);
                mma_bf16(O[n], Ahi, bh0, bh1);
                mma_bf16(O[n], Ahi, bl0, bl1);
                mma_bf16(O[n], Alo, bh0, bh1);
            }
        }
    }

    // ---- epilogue: + bias, split hi/lo, store packed d-pairs ----
    #pragma unroll
    for (int n = 0; n < 4; n++) {
        float2 bv = *(const float2*)&bias[h * 32 + n * 8 + cp * 2];
        float e0 = O[n][0] + bv.x, e1 = O[n][1] + bv.y;   // row r0
        float e2 = O[n][2] + bv.x, e3 = O[n][3] + bv.y;   // row r0+8
        uint32_t p0 = cvt2(e1, e0), p1 = cvt2(e3, e2);
        uint32_t q0 = cvt2(e1 - bfhi(p0), e0 - bflo(p0));
        uint32_t q1 = cvt2(e3 - bfhi(p1), e2 - bflo(p1));
        unsigned i0 = (((unsigned)bh << 10) + l0 + r0) * 16 + n * 4 + cp;
        g_zh[i0] = p0;
        g_zl[i0] = q0;
        g_zh[i0 + 8 * 16] = p1;
        g_zl[i0 + 8 * 16] = q1;
    }
}

// ======================= Kernel 2: mma.sync bf16 flash attention ==============
// Block: 128 queries of one (b,h), 8 warps (16 q-rows each); 16 key tiles of 64.
// S = Qhi*Khi + Qhi*Klo + Qlo*Khi; p = exp2(S*c1 - 32);
// O += Phi*Vhi + Phi*Vlo + Plo*Vhi; lsum exact fp32.
// All K/V B-fragments via ldmatrix from ONE K-major staging buffer:
//   QK: non-trans x4 (2 n-tiles per load); PV: trans x4 reads V^T frags directly.
#define MQ 128
#define NK 64
#define NTILE (LL / NK)

#define QPITCH 80
#define SM_QHI 0
#define SM_QLO (SM_QHI + MQ * QPITCH)        // 10240
#define SM_KHI (SM_QLO + MQ * QPITCH)        // 20480
#define SM_KLO (SM_KHI + NK * QPITCH)        // 25600
#define ATTN_SMEM (SM_KLO + NK * QPITCH)     // 30720

__global__ __launch_bounds__(256, 2) void attn_mma(float* __restrict__ out) {
    extern __shared__ char smc[];
    const uint32_t smb = smem_u32(smc);
    const int tid = threadIdx.x;
    const int wid = tid >> 5, lane = tid & 31;
    const int g = lane >> 2, cp = lane & 3;
    const int bh = blockIdx.x, b = bh >> 3, h = bh & 7;
    const int l0 = blockIdx.y * MQ;
    const float c1 = 0.17677669529663687f * 1.4426950408889634f;  // scale*log2e

    const uint4* zh4 = (const uint4*)g_zh;
    const uint4* zl4 = (const uint4*)g_zl;

    // ---- stage Q (128 rows x 16 u32) hi/lo: pure uint4 copies ----
    #pragma unroll
    for (int i = 0; i < 2; i++) {
        int idx = tid + i * 256;               // 0..511
        int row = idx >> 2, q4 = idx & 3;
        unsigned gi = ((((unsigned)bh << 10) + l0 + row) << 2) + q4;
        *(uint4*)(smc + SM_QHI + row * QPITCH + q4 * 16) = zh4[gi];
        *(uint4*)(smc + SM_QLO + row * QPITCH + q4 * 16) = zl4[gi];
    }
    __syncthreads();

    // ---- load Q fragments once (reused for all 16 key tiles) ----
    uint32_t Ahi[2][4], Alo[2][4];
    {
        const int r0 = wid * 16 + g;
        #pragma unroll
        for (int ks = 0; ks < 2; ks++) {
            int base = ks * 32 + cp * 4;
            Ahi[ks][0] = lds32(smc + SM_QHI + r0 * QPITCH + base);
            Ahi[ks][1] = lds32(smc + SM_QHI + (r0 + 8) * QPITCH + base);
            Ahi[ks][2] = lds32(smc + SM_QHI + r0 * QPITCH + base + 16);
            Ahi[ks][3] = lds32(smc + SM_QHI + (r0 + 8) * QPITCH + base + 16);
            Alo[ks][0] = lds32(smc + SM_QLO + r0 * QPITCH + base);
            Alo[ks][1] = lds32(smc + SM_QLO + (r0 + 8) * QPITCH + base);
            Alo[ks][2] = lds32(smc + SM_QLO + r0 * QPITCH + base + 16);
            Alo[ks][3] = lds32(smc + SM_QLO + (r0 + 8) * QPITCH + base + 16);
        }
    }

    // ldmatrix lane->address bases (computed once)
    // QK x4 tiles: t0=(np2, k8c 2ks) t1=(np2, 2ks+1) t2=(np2+1, 2ks) t3=(np2+1, 2ks+1)
    const uint32_t rowA = 8u * (lane >> 4) + (lane & 7);
    const uint32_t colSel = ((lane >> 3) & 1u) * 16u;
    const uint32_t kaddrh = smb + SM_KHI + rowA * QPITCH + colSel;
    const uint32_t kaddrl = smb + SM_KLO + rowA * QPITCH + colSel;
    // PV trans x4 tiles: 4 consecutive 8-key chunks at d-chunk nt -> row addr = key(lane)
    const uint32_t vaddrh = smb + SM_KHI + (uint32_t)lane * QPITCH;
    const uint32_t vaddrl = smb + SM_KLO + (uint32_t)lane * QPITCH;

    float O[4][4];
    #pragma unroll
    for (int nt = 0; nt < 4; nt++)
        #pragma unroll
        for (int j = 0; j < 4; j++) O[nt][j] = 0.f;
    float lsum0 = 0.f, lsum1 = 0.f;

    for (int t = 0; t < NTILE; t++) {
        __syncthreads();  // previous tile's reads done before restaging
        // ---- stage K tile (64 rows x 16 u32) hi/lo: pure uint4 copies ----
        {
            int k = tid >> 2, q4 = tid & 3;
            unsigned gi = ((((unsigned)bh << 10) + t * NK + k) << 2) + q4;
            *(uint4*)(smc + SM_KHI + k * QPITCH + q4 * 16) = zh4[gi];
            *(uint4*)(smc + SM_KLO + k * QPITCH + q4 * 16) = zl4[gi];
        }
        __syncthreads();

        // ---- QK^T: S (16 x 64 per warp), 3-term split, ldmatrix B-frags ----
        float S[8][4];
        #pragma unroll
        for (int n = 0; n < 8; n++)
            #pragma unroll
            for (int j = 0; j < 4; j++) S[n][j] = 0.f;

        #pragma unroll
        for (int ks = 0; ks < 2; ks++) {
            #pragma unroll
            for (int np = 0; np < 4; np++) {
                uint32_t kh[4], kl[4];
                uint32_t off = (uint32_t)(16 * np * QPITCH + ks * 32);
                ldsm4(kh, kaddrh + off);
                ldsm4(kl, kaddrl + off);
                mma_bf16(S[2 * np], Ahi[ks], kh[0], kh[1]);
                mma_bf16(S[2 * np], Ahi[ks], kl[0], kl[1]);
                mma_bf16(S[2 * np], Alo[ks], kh[0], kh[1]);
                mma_bf16(S[2 * np + 1], Ahi[ks], kh[2], kh[3]);
                mma_bf16(S[2 * np + 1], Ahi[ks], kl[2], kl[3]);
                mma_bf16(S[2 * np + 1], Alo[ks], kh[2], kh[3]);
            }
        }

        // ---- softmax (fixed -32 offset) + pack P as A-frags for PV ----
        uint32_t Phi[4][4], Plo[4][4];
        #pragma unroll
        for (int ks = 0; ks < 4; ks++) {
            float p[2][4];
            #pragma unroll
            for (int half = 0; half < 2; half++) {
                int jn = 2 * ks + half;
                #pragma unroll
                for (int j = 0; j < 4; j++)
                    p[half][j] = ex2f(fmaf(S[jn][j], c1, -32.0f));
            }
            lsum0 += p[0][0] + p[0][1] + p[1][0] + p[1][1];
            lsum1 += p[0][2] + p[0][3] + p[1][2] + p[1][3];
            #pragma unroll
            for (int j = 0; j < 4; j++) {
                int half = j >> 1, lohalf = (j & 1) * 2;
                float e0 = p[half][lohalf], e1 = p[half][lohalf + 1];
                uint32_t ph = cvt2(e1, e0);
                Phi[ks][j] = ph;
                Plo[ks][j] = cvt2(e1 - bfhi(ph), e0 - bflo(ph));
            }
        }

        // ---- PV: O (16 x 32 per warp) += P * V^T, trans-ldmatrix V frags ----
        #pragma unroll
        for (int nt = 0; nt < 4; nt++) {
            uint32_t vh[2][4], vl[2][4];
            ldsm4t(vh[0], vaddrh + nt * 16);
            ldsm4t(vh[1], vaddrh + nt * 16 + 32 * QPITCH);
            ldsm4t(vl[0], vaddrl + nt * 16);
            ldsm4t(vl[1], vaddrl + nt * 16 + 32 * QPITCH);
            #pragma unroll
            for (int ks = 0; ks < 4; ks++) {
                uint32_t b0h = vh[ks >> 1][(ks & 1) * 2];
                uint32_t b1h = vh[ks >> 1][(ks & 1) * 2 + 1];
                uint32_t b0l = vl[ks >> 1][(ks & 1) * 2];
                uint32_t b1l = vl[ks >> 1][(ks & 1) * 2 + 1];
                mma_bf16(O[nt], Phi[ks], b0h, b1h);
                mma_bf16(O[nt], Phi[ks], b0l, b1l);
                mma_bf16(O[nt], Plo[ks], b0h, b1h);
            }
        }
    }

    // ---- normalize + store ----
    lsum0 += __shfl_xor_sync(0xFFFFFFFFu, lsum0, 1);
    lsum0 += __shfl_xor_sync(0xFFFFFFFFu, lsum0, 2);
    lsum1 += __shfl_xor_sync(0xFFFFFFFFu, lsum1, 1);
    lsum1 += __shfl_xor_sync(0xFFFFFFFFu, lsum1, 2);
    const float inv0 = 1.0f / lsum0, inv1 = 1.0f / lsum1;

    const int q0 = l0 + wid * 16 + g, q1 = q0 + 8;
    const unsigned cbase = (unsigned)(b * (HH * DD) + h * DD);
    #pragma unroll
    for (int nt = 0; nt < 4; nt++) {
        int d = nt * 8 + 2 * cp;
        out[((cbase + d) << 10) + q0] = O[nt][0] * inv0;
        out[((cbase + d + 1) << 10) + q0] = O[nt][1] * inv0;
        out[((cbase + d) << 10) + q1] = O[nt][2] * inv1;
        out[((cbase + d + 1) << 10) + q1] = O[nt][3] * inv1;
    }
}

// ======================= launch =======================
extern "C" void kernel_launch(void* const* d_in, const int* in_sizes, int n_in,
                              void* d_out, int out_size) {
    (void)in_sizes; (void)n_in; (void)out_size;
    const float* x = (const float*)d_in[0];   // (8,256,16,64)
    const float* W = (const float*)d_in[1];   // (8,32,256)
    const float* b = (const float*)d_in[2];   // (8,32)
    float* out = (float*)d_out;               // (8,256,16,64)

    cudaFuncSetAttribute(proj_mma, cudaFuncAttributeMaxDynamicSharedMemorySize,
                         PROJ_SMEM);
    cudaFuncSetAttribute(attn_mma, cudaFuncAttributeMaxDynamicSharedMemorySize,
                         ATTN_SMEM);

    proj_mma<<<dim3(BB * HH, 8), 256, PROJ_SMEM>>>(x, W, b);
    attn_mma<<<dim3(BB * HH, LL / MQ), 256, ATTN_SMEM>>>(out);
}

// round 15
// speedup vs baseline: 7.8364x; 1.0456x over previous
#include <cuda_runtime.h>
#include <cstdint>

// Problem constants
#define BB 8
#define CC 256
#define HH 8
#define DD 32
#define LL 1024

// z stored pre-split as packed bf16x2 (d-pairs): [bh][l][16] uint32, 4MB each
__device__ uint32_t g_zh[BB * HH * LL * 16];
__device__ uint32_t g_zl[BB * HH * LL * 16];

// ======================= helpers =======================
static __device__ __forceinline__ float ex2f(float x) {
    float r;
    asm("ex2.approx.f32 %0, %1;" : "=f"(r) : "f"(x));
    return r;
}
// pack two f32 -> bf16x2 (hi arg in upper half, lo arg in lower half)
static __device__ __forceinline__ uint32_t cvt2(float hi, float lo) {
    uint32_t r;
    asm("cvt.rn.bf16x2.f32 %0, %1, %2;" : "=r"(r) : "f"(hi), "f"(lo));
    return r;
}
static __device__ __forceinline__ float bflo(uint32_t packed) {  // low bf16 -> f32
    return __uint_as_float(packed << 16);
}
static __device__ __forceinline__ float bfhi(uint32_t packed) {  // high bf16 -> f32
    return __uint_as_float(packed & 0xFFFF0000u);
}
static __device__ __forceinline__ uint32_t smem_u32(const void* p) {
    uint32_t a;
    asm("{ .reg .u64 t; cvta.to.shared.u64 t, %1; cvt.u32.u64 %0, t; }"
        : "=r"(a) : "l"(p));
    return a;
}

// bf16 mma m16n8k16, row.col, f32 accumulate (baseline PTX, works on sm_103)
static __device__ __forceinline__ void mma_bf16(float* c, const uint32_t* a,
                                                uint32_t b0, uint32_t b1) {
    asm volatile(
        "mma.sync.aligned.m16n8k16.row.col.f32.bf16.bf16.f32 "
        "{%0,%1,%2,%3}, {%4,%5,%6,%7}, {%8,%9}, {%0,%1,%2,%3};"
        : "+f"(c[0]), "+f"(c[1]), "+f"(c[2]), "+f"(c[3])
        : "r"(a[0]), "r"(a[1]), "r"(a[2]), "r"(a[3]), "r"(b0), "r"(b1));
}
// ldmatrix 4-tile loads (baseline PTX sm_75+)
static __device__ __forceinline__ void ldsm4(uint32_t* r, uint32_t a) {
    asm volatile("ldmatrix.sync.aligned.m8n8.x4.shared.b16 {%0,%1,%2,%3}, [%4];"
                 : "=r"(r[0]), "=r"(r[1]), "=r"(r[2]), "=r"(r[3]) : "r"(a));
}
static __device__ __forceinline__ void ldsm4t(uint32_t* r, uint32_t a) {
    asm volatile("ldmatrix.sync.aligned.m8n8.x4.trans.shared.b16 {%0,%1,%2,%3}, [%4];"
                 : "=r"(r[0]), "=r"(r[1]), "=r"(r[2]), "=r"(r[3]) : "r"(a));
}
static __device__ __forceinline__ uint32_t lds32(const char* p) {
    return *(const uint32_t*)p;
}
static __device__ __forceinline__ void sts32(char* p, uint32_t v) {
    *(uint32_t*)p = v;
}
// cp.async 16B (baseline PTX sm_80+)
static __device__ __forceinline__ void cpasync16(uint32_t dst, const void* src) {
    asm volatile("cp.async.cg.shared.global [%0], [%1], 16;"
                 :: "r"(dst), "l"(src) : "memory");
}
#define CP_COMMIT() asm volatile("cp.async.commit_group;" ::: "memory")
#define CP_WAIT0()  asm volatile("cp.async.wait_group 0;" ::: "memory")

// ======================= Kernel 1: tensor-core projection ==================
// Per block: 128 l-rows x 32 d of one (b,h). z = X^T[128,256] * W[h]^T.
// 3-term bf16 split: Xhi*Whi + Xhi*Wlo + Xlo*Whi, fp32 accum, + bias.
// Output: packed bf16x2 hi/lo (d-pairs) into g_zh/g_zl.
#define PW_PITCH 528                       // 132 words = 4 mod 32: banks 4g+cp bijective
#define PA_PITCH 148                       // 37 words odd: conflict-free 4B transpose stores
#define PSM_WHI 0
#define PSM_WLO (PSM_WHI + 32 * PW_PITCH)  // 16896
#define PSM_AHI (PSM_WLO + 32 * PW_PITCH)  // 33792
#define PSM_ALO (PSM_AHI + 128 * PA_PITCH) // 52736
#define PROJ_SMEM (PSM_ALO + 128 * PA_PITCH) // 71680

__global__ __launch_bounds__(256, 2) void proj_mma(
    const float* __restrict__ x, const float* __restrict__ Wt,
    const float* __restrict__ bias) {
    extern __shared__ char smc[];
    const int tid = threadIdx.x;
    const int wid = tid >> 5, lane = tid & 31;
    const int g = lane >> 2, cp = lane & 3;
    const int bh = blockIdx.x, b = bh >> 3, h = bh & 7;
    const int l0 = blockIdx.y * 128;

    // ---- stage W[h] (32 x 256) as bf16 hi/lo (PW_PITCH mult of 16: uint2 ok) ----
    #pragma unroll
    for (int i = 0; i < 8; i++) {
        int idx = tid + i * 256;           // 0..2047
        int d = idx >> 6, cq = idx & 63;   // cq = group of 4 c's
        float4 v = *(const float4*)&Wt[(h * 32 + d) * 256 + cq * 4];
        uint32_t ph0 = cvt2(v.y, v.x), ph1 = cvt2(v.w, v.z);
        uint32_t pl0 = cvt2(v.y - bfhi(ph0), v.x - bflo(ph0));
        uint32_t pl1 = cvt2(v.w - bfhi(ph1), v.z - bflo(ph1));
        *(uint2*)(smc + PSM_WHI + d * PW_PITCH + cq * 8) = make_uint2(ph0, ph1);
        *(uint2*)(smc + PSM_WLO + d * PW_PITCH + cq * 8) = make_uint2(pl0, pl1);
    }

    float O[4][4];
    #pragma unroll
    for (int n = 0; n < 4; n++)
        #pragma unroll
        for (int j = 0; j < 4; j++) O[n][j] = 0.f;

    const int r0 = wid * 16 + g;

    for (int kc = 0; kc < 4; kc++) {       // K chunks of 64 c
        __syncthreads();                    // W ready (kc=0) / prev chunk mma done
        // ---- stage transposed X tile: A[l][c] (128 x 64) hi/lo bf16 ----
        // thread: one l, 4 consecutive c. PA_PITCH = 4 mod 8 -> MUST use 4B stores.
        #pragma unroll
        for (int i = 0; i < 8; i++) {
            int idx = tid + i * 256;        // 0..2047
            int l = idx & 127, cg = idx >> 7;  // cg = group of 4 c
            const float* xp = &x[((unsigned)(b * CC + kc * 64 + cg * 4) << 10) + l0 + l];
            float v0 = xp[0];
            float v1 = xp[1 << 10];
            float v2 = xp[2 << 10];
            float v3 = xp[3 << 10];
            uint32_t ph0 = cvt2(v1, v0), ph1 = cvt2(v3, v2);
            uint32_t pl0 = cvt2(v1 - bfhi(ph0), v0 - bflo(ph0));
            uint32_t pl1 = cvt2(v3 - bfhi(ph1), v2 - bflo(ph1));
            char* ah = smc + PSM_AHI + l * PA_PITCH + cg * 8;
            char* al = smc + PSM_ALO + l * PA_PITCH + cg * 8;
            sts32(ah, ph0);
            sts32(ah + 4, ph1);
            sts32(al, pl0);
            sts32(al + 4, pl1);
        }
        __syncthreads();

        // ---- mma: 4 k-steps x 4 n-tiles x 3 split terms ----
        #pragma unroll
        for (int ks = 0; ks < 4; ks++) {
            uint32_t Ahi[4], Alo[4];
            const char* ab = smc + r0 * PA_PITCH + ks * 32 + cp * 4;
            Ahi[0] = lds32(ab + PSM_AHI);
            Ahi[1] = lds32(ab + PSM_AHI + 8 * PA_PITCH);
            Ahi[2] = lds32(ab + PSM_AHI + 16);
            Ahi[3] = lds32(ab + PSM_AHI + 8 * PA_PITCH + 16);
            Alo[0] = lds32(ab + PSM_ALO);
            Alo[1] = lds32(ab + PSM_ALO + 8 * PA_PITCH);
            Alo[2] = lds32(ab + PSM_ALO + 16);
            Alo[3] = lds32(ab + PSM_ALO + 8 * PA_PITCH + 16);
            #pragma unroll
            for (int n = 0; n < 4; n++) {
                const char* wb = smc + (n * 8 + g) * PW_PITCH + kc * 128 + ks * 32 + cp * 4;
                uint32_t bh0 = lds32(wb + PSM_WHI);
                uint32_t bh1 = lds32(wb + PSM_WHI + 16);
                uint32_t bl0 = lds32(wb + PSM_WLO);
                uint32_t bl1 = lds32(wb + PSM_WLO + 16);
                mma_bf16(O[n], Ahi, bh0, bh1);
                mma_bf16(O[n], Ahi, bl0, bl1);
                mma_bf16(O[n], Alo, bh0, bh1);
            }
        }
    }

    // ---- epilogue: + bias, split hi/lo, store packed d-pairs ----
    #pragma unroll
    for (int n = 0; n < 4; n++) {
        float2 bv = *(const float2*)&bias[h * 32 + n * 8 + cp * 2];
        float e0 = O[n][0] + bv.x, e1 = O[n][1] + bv.y;   // row r0
        float e2 = O[n][2] + bv.x, e3 = O[n][3] + bv.y;   // row r0+8
        uint32_t p0 = cvt2(e1, e0), p1 = cvt2(e3, e2);
        uint32_t q0 = cvt2(e1 - bfhi(p0), e0 - bflo(p0));
        uint32_t q1 = cvt2(e3 - bfhi(p1), e2 - bflo(p1));
        unsigned i0 = (((unsigned)bh << 10) + l0 + r0) * 16 + n * 4 + cp;
        g_zh[i0] = p0;
        g_zl[i0] = q0;
        g_zh[i0 + 8 * 16] = p1;
        g_zl[i0 + 8 * 16] = q1;
    }
}

// ======================= Kernel 2: mma.sync bf16 flash attention ==============
// Block: 128 queries of one (b,h), 8 warps (16 q-rows each); 16 key tiles of 64.
// S = Qhi*Khi + Qhi*Klo + Qlo*Khi; p = exp2(S*c1 - 32);
// O += Phi*Vhi + Phi*Vlo + Plo*Vhi; lsum exact fp32.
// K staged via cp.async DOUBLE BUFFER: tile t+1 copy overlaps tile t compute;
// one __syncthreads per tile. All K/V B-frags via ldmatrix (PV uses .trans).
#define MQ 128
#define NK 64
#define NTILE (LL / NK)

#define QPITCH 80
#define SM_QHI 0
#define SM_QLO (SM_QHI + MQ * QPITCH)        // 10240
#define SM_K   (SM_QLO + MQ * QPITCH)        // 20480: two buffers of (KHI|KLO)
#define KHALF  (NK * QPITCH)                 // 5120
#define KBUF   (2 * KHALF)                   // 10240 per buffer
#define ATTN_SMEM (SM_K + 2 * KBUF)          // 40960

__global__ __launch_bounds__(256, 2) void attn_mma(float* __restrict__ out) {
    extern __shared__ char smc[];
    const uint32_t smb = smem_u32(smc);
    const int tid = threadIdx.x;
    const int wid = tid >> 5, lane = tid & 31;
    const int g = lane >> 2, cp = lane & 3;
    const int bh = blockIdx.x, b = bh >> 3, h = bh & 7;
    const int l0 = blockIdx.y * MQ;
    const float c1 = 0.17677669529663687f * 1.4426950408889634f;  // scale*log2e

    const uint4* zh4 = (const uint4*)g_zh;
    const uint4* zl4 = (const uint4*)g_zl;

    // per-thread K-staging slot: one uint4 of hi + one of lo per tile
    const int kst = tid >> 2, kq4 = tid & 3;
    const uint32_t kdst = smb + SM_K + (uint32_t)(kst * QPITCH + kq4 * 16);
    const unsigned kgi_base = (((unsigned)bh << 10) + kst) * 4 + kq4;

    // ---- prefetch K tile 0 into buffer 0 ----
    cpasync16(kdst, &zh4[kgi_base]);
    cpasync16(kdst + KHALF, &zl4[kgi_base]);
    CP_COMMIT();

    // ---- stage Q (128 rows x 16 u32) hi/lo: pure uint4 copies ----
    #pragma unroll
    for (int i = 0; i < 2; i++) {
        int idx = tid + i * 256;               // 0..511
        int row = idx >> 2, q4 = idx & 3;
        unsigned gi = ((((unsigned)bh << 10) + l0 + row) << 2) + q4;
        *(uint4*)(smc + SM_QHI + row * QPITCH + q4 * 16) = zh4[gi];
        *(uint4*)(smc + SM_QLO + row * QPITCH + q4 * 16) = zl4[gi];
    }
    CP_WAIT0();
    __syncthreads();

    // ---- load Q fragments once (reused for all 16 key tiles) ----
    uint32_t Ahi[2][4], Alo[2][4];
    {
        const int r0 = wid * 16 + g;
        #pragma unroll
        for (int ks = 0; ks < 2; ks++) {
            int base = ks * 32 + cp * 4;
            Ahi[ks][0] = lds32(smc + SM_QHI + r0 * QPITCH + base);
            Ahi[ks][1] = lds32(smc + SM_QHI + (r0 + 8) * QPITCH + base);
            Ahi[ks][2] = lds32(smc + SM_QHI + r0 * QPITCH + base + 16);
            Ahi[ks][3] = lds32(smc + SM_QHI + (r0 + 8) * QPITCH + base + 16);
            Alo[ks][0] = lds32(smc + SM_QLO + r0 * QPITCH + base);
            Alo[ks][1] = lds32(smc + SM_QLO + (r0 + 8) * QPITCH + base);
            Alo[ks][2] = lds32(smc + SM_QLO + r0 * QPITCH + base + 16);
            Alo[ks][3] = lds32(smc + SM_QLO + (r0 + 8) * QPITCH + base + 16);
        }
    }

    // ldmatrix lane->address bases within a K buffer (hi at +0, lo at +KHALF)
    const uint32_t rowA = 8u * (lane >> 4) + (lane & 7);
    const uint32_t colSel = ((lane >> 3) & 1u) * 16u;
    const uint32_t kaddr0 = smb + SM_K + rowA * QPITCH + colSel;   // QK frags
    const uint32_t vaddr0 = smb + SM_K + (uint32_t)lane * QPITCH;  // PV trans frags

    float O[4][4];
    #pragma unroll
    for (int nt = 0; nt < 4; nt++)
        #pragma unroll
        for (int j = 0; j < 4; j++) O[nt][j] = 0.f;
    float lsum0 = 0.f, lsum1 = 0.f;

    for (int t = 0; t < NTILE; t++) {
        const uint32_t bufo = (uint32_t)(t & 1) * KBUF;

        // ---- prefetch next K tile into the other buffer (overlaps compute) ----
        if (t + 1 < NTILE) {
            uint32_t nd = kdst + ((uint32_t)((t + 1) & 1)) * KBUF;
            unsigned gi = kgi_base + (unsigned)(t + 1) * NK * 4;
            cpasync16(nd, &zh4[gi]);
            cpasync16(nd + KHALF, &zl4[gi]);
            CP_COMMIT();
        }

        // ---- QK^T: S (16 x 64 per warp), 3-term split, ldmatrix B-frags ----
        float S[8][4];
        #pragma unroll
        for (int n = 0; n < 8; n++)
            #pragma unroll
            for (int j = 0; j < 4; j++) S[n][j] = 0.f;

        const uint32_t kaddrh = kaddr0 + bufo, kaddrl = kaddrh + KHALF;
        #pragma unroll
        for (int ks = 0; ks < 2; ks++) {
            #pragma unroll
            for (int np = 0; np < 4; np++) {
                uint32_t kh[4], kl[4];
                uint32_t off = (uint32_t)(16 * np * QPITCH + ks * 32);
                ldsm4(kh, kaddrh + off);
                ldsm4(kl, kaddrl + off);
                mma_bf16(S[2 * np], Ahi[ks], kh[0], kh[1]);
                mma_bf16(S[2 * np], Ahi[ks], kl[0], kl[1]);
                mma_bf16(S[2 * np], Alo[ks], kh[0], kh[1]);
                mma_bf16(S[2 * np + 1], Ahi[ks], kh[2], kh[3]);
                mma_bf16(S[2 * np + 1], Ahi[ks], kl[2], kl[3]);
                mma_bf16(S[2 * np + 1], Alo[ks], kh[2], kh[3]);
            }
        }

        // ---- softmax (fixed -32 offset) + pack P as A-frags for PV ----
        uint32_t Phi[4][4], Plo[4][4];
        #pragma unroll
        for (int ks = 0; ks < 4; ks++) {
            float p[2][4];
            #pragma unroll
            for (int half = 0; half < 2; half++) {
                int jn = 2 * ks + half;
                #pragma unroll
                for (int j = 0; j < 4; j++)
                    p[half][j] = ex2f(fmaf(S[jn][j], c1, -32.0f));
            }
            lsum0 += p[0][0] + p[0][1] + p[1][0] + p[1][1];
            lsum1 += p[0][2] + p[0][3] + p[1][2] + p[1][3];
            #pragma unroll
            for (int j = 0; j < 4; j++) {
                int half = j >> 1, lohalf = (j & 1) * 2;
                float e0 = p[half][lohalf], e1 = p[half][lohalf + 1];
                uint32_t ph = cvt2(e1, e0);
                Phi[ks][j] = ph;
                Plo[ks][j] = cvt2(e1 - bfhi(ph), e0 - bflo(ph));
            }
        }

        // ---- PV: O (16 x 32 per warp) += P * V^T, trans-ldmatrix V frags ----
        const uint32_t vaddrh = vaddr0 + bufo, vaddrl = vaddrh + KHALF;
        #pragma unroll
        for (int nt = 0; nt < 4; nt++) {
            uint32_t vh[2][4], vl[2][4];
            ldsm4t(vh[0], vaddrh + nt * 16);
            ldsm4t(vh[1], vaddrh + nt * 16 + 32 * QPITCH);
            ldsm4t(vl[0], vaddrl + nt * 16);
            ldsm4t(vl[1], vaddrl + nt * 16 + 32 * QPITCH);
            #pragma unroll
            for (int ks = 0; ks < 4; ks++) {
                uint32_t b0h = vh[ks >> 1][(ks & 1) * 2];
                uint32_t b1h = vh[ks >> 1][(ks & 1) * 2 + 1];
                uint32_t b0l = vl[ks >> 1][(ks & 1) * 2];
                uint32_t b1l = vl[ks >> 1][(ks & 1) * 2 + 1];
                mma_bf16(O[nt], Phi[ks], b0h, b1h);
                mma_bf16(O[nt], Phi[ks], b0l, b1l);
                mma_bf16(O[nt], Plo[ks], b0h, b1h);
            }
        }

        // next tile's cp.async must be complete and all warps done before reuse
        if (t + 1 < NTILE) {
            CP_WAIT0();
            __syncthreads();
        }
    }

    // ---- normalize + store ----
    lsum0 += __shfl_xor_sync(0xFFFFFFFFu, lsum0, 1);
    lsum0 += __shfl_xor_sync(0xFFFFFFFFu, lsum0, 2);
    lsum1 += __shfl_xor_sync(0xFFFFFFFFu, lsum1, 1);
    lsum1 += __shfl_xor_sync(0xFFFFFFFFu, lsum1, 2);
    const float inv0 = 1.0f / lsum0, inv1 = 1.0f / lsum1;

    const int q0 = l0 + wid * 16 + g, q1 = q0 + 8;
    const unsigned cbase = (unsigned)(b * (HH * DD) + h * DD);
    #pragma unroll
    for (int nt = 0; nt < 4; nt++) {
        int d = nt * 8 + 2 * cp;
        out[((cbase + d) << 10) + q0] = O[nt][0] * inv0;
        out[((cbase + d + 1) << 10) + q0] = O[nt][1] * inv0;
        out[((cbase + d) << 10) + q1] = O[nt][2] * inv1;
        out[((cbase + d + 1) << 10) + q1] = O[nt][3] * inv1;
    }
}

// ======================= launch =======================
extern "C" void kernel_launch(void* const* d_in, const int* in_sizes, int n_in,
                              void* d_out, int out_size) {
    (void)in_sizes; (void)n_in; (void)out_size;
    const float* x = (const float*)d_in[0];   // (8,256,16,64)
    const float* W = (const float*)d_in[1];   // (8,32,256)
    const float* b = (const float*)d_in[2];   // (8,32)
    float* out = (float*)d_out;               // (8,256,16,64)

    cudaFuncSetAttribute(proj_mma, cudaFuncAttributeMaxDynamicSharedMemorySize,
                         PROJ_SMEM);
    cudaFuncSetAttribute(attn_mma, cudaFuncAttributeMaxDynamicSharedMemorySize,
                         ATTN_SMEM);

    proj_mma<<<dim3(BB * HH, 8), 256, PROJ_SMEM>>>(x, W, b);
    attn_mma<<<dim3(BB * HH, LL / MQ), 256, ATTN_SMEM>>>(out);
}